// round 4
// baseline (speedup 1.0000x reference)
#include <cuda_runtime.h>
#include <cuda_bf16.h>
#include <math.h>

#define Hh   8
#define Dm   128
#define Ee   128
#define KDk  16
#define Bb   16
#define NPICK 250
#define NDEL  250
#define Gg   501            // 1 + NPICK + NDEL
#define NTOK (Bb*Gg)        // 8016
#define GPAD 512            // padded row length for g_heads2

typedef unsigned long long u64;

// ---------------- packed f32x2 helpers (FFMA2 path, 2x fp32 rate) ----------
__device__ __forceinline__ u64 fma2(u64 a, u64 b, u64 c) {
    u64 d; asm("fma.rn.f32x2 %0, %1, %2, %3;" : "=l"(d) : "l"(a), "l"(b), "l"(c));
    return d;
}
__device__ __forceinline__ u64 mul2(u64 a, u64 b) {
    u64 d; asm("mul.rn.f32x2 %0, %1, %2;" : "=l"(d) : "l"(a), "l"(b));
    return d;
}
__device__ __forceinline__ u64 add2(u64 a, u64 b) {
    u64 d; asm("add.rn.f32x2 %0, %1, %2;" : "=l"(d) : "l"(a), "l"(b));
    return d;
}
__device__ __forceinline__ void upk(u64 a, float& x, float& y) {
    asm("mov.b64 {%0, %1}, %2;" : "=f"(x), "=f"(y) : "l"(a));
}
__device__ __forceinline__ u64 dup2(float x) {
    u64 r; asm("mov.b64 %0, {%1, %1};" : "=l"(r) : "f"(x));
    return r;
}
__device__ __forceinline__ float ex2f(float x) {
    float r; asm("ex2.approx.ftz.f32 %0, %1;" : "=f"(r) : "f"(x));
    return r;
}

// ---------------- device scratch ----------------
#define WPAD 130
__device__ float g_Wt[Hh*7*KDk*WPAD];       // transposed+padded weights
__device__ float g_K [Hh*Bb*Gg*KDk];
__device__ float g_V [Hh*Bb*Gg*KDk];
__device__ float g_Qm[Hh*Bb*Gg*KDk];        // pre-scaled by nf*log2(e)
__device__ float g_QA[Hh*Bb*Gg*KDk];
__device__ float g_QB[Hh*Bb*Gg*KDk];
__device__ float g_heads2[Bb*128*GPAD];     // [b][h*16+v][g] hv-major, rows padded

#define SCL   (0.25f * 1.44269504f)    // 1/sqrt(KD) * log2(e)
#define M2OFF 16.0f                    // fixed softmax offset (log2 units)

// ==========================================================================
// Kernel 0: weight prep.  g_Wt[h][m*16+k][d] = W_m[h][d][k]  (row pad 130)
// ==========================================================================
__global__ void wprep_kernel(const float* __restrict__ Wq, const float* __restrict__ Wk,
                             const float* __restrict__ Wv, const float* __restrict__ W1,
                             const float* __restrict__ W2, const float* __restrict__ W3,
                             const float* __restrict__ W4)
{
    const float* Ws[7] = {Wq, Wk, Wv, W1, W2, W3, W4};
    const int m = blockIdx.x, h = blockIdx.y;
    const float* w = Ws[m] + h * (Dm*KDk);
    float* dst = g_Wt + (size_t)(h*7*KDk + m*KDk) * WPAD;
    for (int idx = threadIdx.x; idx < Dm*KDk; idx += 256) {
        int d = idx >> 4, k = idx & 15;
        dst[k*WPAD + d] = w[idx];
    }
}

// ==========================================================================
// Kernel 1: projections.  Block = (80-token chunk, head), 256 threads.
// thread (k = tid&15, tg = tid>>4): 5 tokens x 7 mats, fma2 inner loop.
// BOTH weight rows and q rows padded to 130 floats -> conflict-free LDS.64.
// ==========================================================================
#define PT_TOK 80
#define QPAD   130
#define K1_SMEM ((7*16*WPAD + PT_TOK*QPAD)*4)   // 99840 B

__global__ void __launch_bounds__(256) proj_kernel(const float* __restrict__ q)
{
    extern __shared__ float sm[];
    float* Wt = sm;                         // 112*130
    float* qs = sm + 7*KDk*WPAD;            // 80*130

    const int h    = blockIdx.y;
    const int base = blockIdx.x * PT_TOK;
    const int tid  = threadIdx.x;
    const int nTok = min(PT_TOK, NTOK - base);

    {   // stage padded weights (contiguous float2 copy, L2-hot)
        const float2* src = (const float2*)(g_Wt + (size_t)h*7*KDk*WPAD);
        float2*       dst = (float2*)Wt;
#pragma unroll
        for (int i = 0; i < 29; i++) {      // 29*256 = 7424 >= 7280
            int idx = tid + i*256;
            if (idx < 7*KDk*WPAD/2) dst[idx] = src[idx];
        }
    }
    {   // stage q rows with padding (float2 granularity)
        const float2* qg = (const float2*)(q + (size_t)base * Dm);
        const int n2 = nTok * (Dm/2);
        for (int idx = tid; idx < n2; idx += 256) {
            int t = idx >> 6, i = idx & 63;
            ((float2*)(qs + t*QPAD))[i] = qg[idx];
        }
    }
    __syncthreads();

    const int k  = tid & 15;
    const int tg = tid >> 4;                // 16 groups x 5 tokens
    const int t0 = tg * 5;

    u64 acc[5][7];
#pragma unroll
    for (int i = 0; i < 5; i++)
#pragma unroll
        for (int m = 0; m < 7; m++) acc[i][m] = 0ull;

    const u64* qr[5];
#pragma unroll
    for (int i = 0; i < 5; i++) qr[i] = (const u64*)(qs + (t0 + i)*QPAD);
    const u64* wr[7];
#pragma unroll
    for (int m = 0; m < 7; m++) wr[m] = (const u64*)(Wt + (m*16 + k)*WPAD);

#pragma unroll 2
    for (int d2 = 0; d2 < Dm/2; d2++) {
        u64 qv[5];
#pragma unroll
        for (int i = 0; i < 5; i++) qv[i] = qr[i][d2];
#pragma unroll
        for (int m = 0; m < 7; m++) {
            u64 w = wr[m][d2];
#pragma unroll
            for (int i = 0; i < 5; i++) acc[i][m] = fma2(qv[i], w, acc[i][m]);
        }
    }

#pragma unroll
    for (int i = 0; i < 5; i++) {
        if (t0 + i >= nTok) break;
        float s[7];
#pragma unroll
        for (int m = 0; m < 7; m++) { float x, y; upk(acc[i][m], x, y); s[m] = x + y; }
        const int token = base + t0 + i;
        const int b = token / Gg;
        const int g = token - b * Gg;
        const bool pick = (g >= 1 && g <= NPICK);
        const int idx = ((h*Bb + b)*Gg + g)*KDk + k;
        g_Qm[idx] = s[0] * SCL;
        g_K [idx] = s[1];
        g_V [idx] = s[2];
        g_QA[idx] = (pick ? s[3] : s[5]) * SCL;
        g_QB[idx] = (pick ? s[4] : s[6]) * SCL;
    }
}

// ==========================================================================
// Kernel 2: fused attention.  One block per (h,b), 512 threads, one q-row
// per thread.  Fixed-offset exp2 softmax, packed f32x2 dot + AV accumulate.
// Output written hv-major into g_heads2 (coalesced per-v columns).
// ==========================================================================
#define K2_SMEM (2*Gg*KDk*4)   // 64128 B

__global__ void __launch_bounds__(512) attn_kernel()
{
    extern __shared__ float sm[];

    const int b  = blockIdx.x;
    const int h  = blockIdx.y;
    const int tid = threadIdx.x;
    const int hb  = h*Bb + b;

    {   // stage K,V for this (h,b): 501 x 16 floats each
        const float4* Kg = (const float4*)(g_K + (size_t)hb * Gg * KDk);
        const float4* Vg = (const float4*)(g_V + (size_t)hb * Gg * KDk);
        float4* Ks4 = (float4*)sm;
        float4* Vs4 = (float4*)(sm + Gg*KDk);
        for (int i = tid; i < Gg*4; i += 512) { Ks4[i] = Kg[i]; Vs4[i] = Vg[i]; }
    }
    __syncthreads();

    const int qrow = tid;
    if (qrow >= Gg) return;

    const u64* Ks = (const u64*)sm;
    const u64* Vs = Ks + Gg*8;

    const int qidx = (hb*Gg + qrow)*KDk;
    u64 qm[8];
    {
        const u64* qp = (const u64*)(g_Qm + qidx);
#pragma unroll
        for (int j = 0; j < 8; j++) qm[j] = qp[j];
    }

    float l = 0.f;
    u64 o[8];
#pragma unroll
    for (int j = 0; j < 8; j++) o[j] = 0ull;

    // ---- main block: 501 keys, no mask ----
#pragma unroll 2
    for (int g = 0; g < Gg; g++) {
        const u64* kr = Ks + g*8;
        u64 a0 = mul2(qm[0], kr[0]);
        u64 a1 = mul2(qm[1], kr[1]);
        a0 = fma2(qm[2], kr[2], a0);
        a1 = fma2(qm[3], kr[3], a1);
        a0 = fma2(qm[4], kr[4], a0);
        a1 = fma2(qm[5], kr[5], a1);
        a0 = fma2(qm[6], kr[6], a0);
        a1 = fma2(qm[7], kr[7], a1);
        a0 = add2(a0, a1);
        float x, y; upk(a0, x, y);
        float s = x + y;
        float p = ex2f(s - M2OFF);
        l += p;
        u64 pp = dup2(p);
        const u64* vr = Vs + g*8;
#pragma unroll
        for (int j = 0; j < 8; j++) o[j] = fma2(pp, vr[j], o[j]);
    }

    // ---- extra blocks (rows 1..500 only), zmask: score==0 -> excluded ----
    if (qrow >= 1) {
        u64 qa[8], qb[8];
        {
            const u64* pa = (const u64*)(g_QA + qidx);
            const u64* pb = (const u64*)(g_QB + qidx);
#pragma unroll
            for (int j = 0; j < 8; j++) { qa[j] = pa[j]; qb[j] = pb[j]; }
        }
        const u64* Kp = Ks + 1*8;
        const u64* Vp = Vs + 1*8;
#pragma unroll 2
        for (int g = 0; g < NPICK; g++) {
            const u64* kr = Kp + g*8;
            u64 a0 = mul2(qa[0], kr[0]);
            u64 a1 = mul2(qa[1], kr[1]);
            a0 = fma2(qa[2], kr[2], a0);
            a1 = fma2(qa[3], kr[3], a1);
            a0 = fma2(qa[4], kr[4], a0);
            a1 = fma2(qa[5], kr[5], a1);
            a0 = fma2(qa[6], kr[6], a0);
            a1 = fma2(qa[7], kr[7], a1);
            a0 = add2(a0, a1);
            float x, y; upk(a0, x, y);
            float s = x + y;
            float p = ex2f(s - M2OFF);
            p = (s == 0.f) ? 0.f : p;
            l += p;
            u64 pp = dup2(p);
            const u64* vr = Vp + g*8;
#pragma unroll
            for (int j = 0; j < 8; j++) o[j] = fma2(pp, vr[j], o[j]);
        }
        const u64* Kd = Ks + (1+NPICK)*8;
        const u64* Vd = Vs + (1+NPICK)*8;
#pragma unroll 2
        for (int g = 0; g < NDEL; g++) {
            const u64* kr = Kd + g*8;
            u64 a0 = mul2(qb[0], kr[0]);
            u64 a1 = mul2(qb[1], kr[1]);
            a0 = fma2(qb[2], kr[2], a0);
            a1 = fma2(qb[3], kr[3], a1);
            a0 = fma2(qb[4], kr[4], a0);
            a1 = fma2(qb[5], kr[5], a1);
            a0 = fma2(qb[6], kr[6], a0);
            a1 = fma2(qb[7], kr[7], a1);
            a0 = add2(a0, a1);
            float x, y; upk(a0, x, y);
            float s = x + y;
            float p = ex2f(s - M2OFF);
            p = (s == 0.f) ? 0.f : p;
            l += p;
            u64 pp = dup2(p);
            const u64* vr = Vd + g*8;
#pragma unroll
            for (int j = 0; j < 8; j++) o[j] = fma2(pp, vr[j], o[j]);
        }
    }

    const float inv = 1.f / l;
    const u64 iv = dup2(inv);
    // hv-major write: g_heads2[b][h*16+v][qrow]
    float* hp = g_heads2 + ((size_t)b*128 + h*16)*GPAD + qrow;
#pragma unroll
    for (int j = 0; j < 8; j++) {
        float x, y; upk(mul2(o[j], iv), x, y);
        hp[(2*j  )*GPAD] = x;
        hp[(2*j+1)*GPAD] = y;
    }
}

// ==========================================================================
// Kernel 3: out[b,g,e] = sum_hv heads2[b][hv][g] * W_out[hv][e]
// Block = (56-token tile, b), 256 threads. Thread: column e, 14 token-pairs.
// ==========================================================================
#define OT_TT  56
#define OT_ROW 58      // padded smem row (floats), even -> u64-aligned
#define K3_SMEM (128*OT_ROW*4)   // 29696 B

__global__ void __launch_bounds__(256) out_kernel(const float* __restrict__ Wo,
                                                  float* __restrict__ out)
{
    extern __shared__ float sm[];
    const int b   = blockIdx.y;
    const int g0  = blockIdx.x * OT_TT;
    const int tid = threadIdx.x;

    // stage heads tile: 128 rows x 56 tokens (rows of g_heads2 are GPAD-padded,
    // cols >= Gg are never written and stay zero-initialized -> safe to read)
    for (int idx = tid; idx < 128*OT_TT; idx += 256) {
        int hv = idx / OT_TT, t = idx - hv*OT_TT;
        sm[hv*OT_ROW + t] = g_heads2[((size_t)b*128 + hv)*GPAD + g0 + t];
    }
    __syncthreads();

    const int e    = tid & 127;
    const int half = tid >> 7;           // 0/1 -> token pairs [half*14, half*14+14)

    u64 acc[14];
#pragma unroll
    for (int j = 0; j < 14; j++) acc[j] = 0ull;

#pragma unroll 4
    for (int hv = 0; hv < 128; hv++) {
        const float w = __ldg(Wo + hv*Ee + e);
        const u64 wd = dup2(w);
        const u64* row = (const u64*)(sm + hv*OT_ROW) + half*14;
#pragma unroll
        for (int j = 0; j < 14; j++) acc[j] = fma2(row[j], wd, acc[j]);
    }

#pragma unroll
    for (int j = 0; j < 14; j++) {
        int g = g0 + 2*(half*14 + j);
        float x, y; upk(acc[j], x, y);
        if (g     < Gg) out[((size_t)b*Gg + g    )*Ee + e] = x;
        if (g + 1 < Gg) out[((size_t)b*Gg + g + 1)*Ee + e] = y;
    }
}

// ==========================================================================
extern "C" void kernel_launch(void* const* d_in, const int* in_sizes, int n_in,
                              void* d_out, int out_size)
{
    const float* q  = (const float*)d_in[0];
    const float* Wq = (const float*)d_in[1];
    const float* Wk = (const float*)d_in[2];
    const float* Wv = (const float*)d_in[3];
    const float* W1 = (const float*)d_in[4];
    const float* W2 = (const float*)d_in[5];
    const float* W3 = (const float*)d_in[6];
    const float* W4 = (const float*)d_in[7];
    const float* Wo = (const float*)d_in[8];
    float* out = (float*)d_out;

    cudaFuncSetAttribute(proj_kernel, cudaFuncAttributeMaxDynamicSharedMemorySize, K1_SMEM);
    cudaFuncSetAttribute(attn_kernel, cudaFuncAttributeMaxDynamicSharedMemorySize, K2_SMEM);
    cudaFuncSetAttribute(out_kernel,  cudaFuncAttributeMaxDynamicSharedMemorySize, K3_SMEM);

    dim3 g0(7, Hh);
    wprep_kernel<<<g0, 256>>>(Wq, Wk, Wv, W1, W2, W3, W4);

    dim3 g1((NTOK + PT_TOK - 1)/PT_TOK, Hh);        // (101, 8)
    proj_kernel<<<g1, 256, K1_SMEM>>>(q);

    dim3 g2(Bb, Hh);                                // (16, 8) x 512 threads
    attn_kernel<<<g2, 512, K2_SMEM>>>();

    dim3 g3((Gg + OT_TT - 1)/OT_TT, Bb);            // (9, 16)
    out_kernel<<<g3, 256, K3_SMEM>>>(Wo, out);
}

// round 5
// speedup vs baseline: 1.0300x; 1.0300x over previous
#include <cuda_runtime.h>
#include <cuda_bf16.h>
#include <math.h>

#define Hh   8
#define Dm   128
#define Ee   128
#define KDk  16
#define Bb   16
#define NPICK 250
#define NDEL  250
#define Gg   501            // 1 + NPICK + NDEL
#define NTOK (Bb*Gg)        // 8016
#define GPAD 512            // padded row length for g_heads2

typedef unsigned long long u64;

// ---------------- packed f32x2 helpers (FFMA2 path, 2x fp32 rate) ----------
__device__ __forceinline__ u64 fma2(u64 a, u64 b, u64 c) {
    u64 d; asm("fma.rn.f32x2 %0, %1, %2, %3;" : "=l"(d) : "l"(a), "l"(b), "l"(c));
    return d;
}
__device__ __forceinline__ u64 mul2(u64 a, u64 b) {
    u64 d; asm("mul.rn.f32x2 %0, %1, %2;" : "=l"(d) : "l"(a), "l"(b));
    return d;
}
__device__ __forceinline__ u64 add2(u64 a, u64 b) {
    u64 d; asm("add.rn.f32x2 %0, %1, %2;" : "=l"(d) : "l"(a), "l"(b));
    return d;
}
__device__ __forceinline__ void upk(u64 a, float& x, float& y) {
    asm("mov.b64 {%0, %1}, %2;" : "=f"(x), "=f"(y) : "l"(a));
}
__device__ __forceinline__ u64 dup2(float x) {
    u64 r; asm("mov.b64 %0, {%1, %1};" : "=l"(r) : "f"(x));
    return r;
}
__device__ __forceinline__ float ex2f(float x) {
    float r; asm("ex2.approx.ftz.f32 %0, %1;" : "=f"(r) : "f"(x));
    return r;
}

// ---------------- device scratch ----------------
#define WPAD 130
__device__ float g_Wt[Hh*7*KDk*WPAD];       // transposed+padded weights
__device__ float g_K [Hh*Bb*Gg*KDk];
__device__ float g_V [Hh*Bb*Gg*KDk];
__device__ float g_Qm[Hh*Bb*Gg*KDk];        // pre-scaled by nf*log2(e)
__device__ float g_QA[Hh*Bb*Gg*KDk];
__device__ float g_QB[Hh*Bb*Gg*KDk];
__device__ float g_heads2[Bb*128*GPAD];     // [b][h*16+v][g] hv-major, rows padded

#define SCL   (0.25f * 1.44269504f)    // 1/sqrt(KD) * log2(e)
#define M2OFF 16.0f                    // fixed softmax offset (log2 units)

// ==========================================================================
// Kernel 0: weight prep.  g_Wt[h][m*16+k][d] = W_m[h][d][k]  (row pad 130)
// ==========================================================================
__global__ void wprep_kernel(const float* __restrict__ Wq, const float* __restrict__ Wk,
                             const float* __restrict__ Wv, const float* __restrict__ W1,
                             const float* __restrict__ W2, const float* __restrict__ W3,
                             const float* __restrict__ W4)
{
    const float* Ws[7] = {Wq, Wk, Wv, W1, W2, W3, W4};
    const int m = blockIdx.x, h = blockIdx.y;
    const float* w = Ws[m] + h * (Dm*KDk);
    float* dst = g_Wt + (size_t)(h*7*KDk + m*KDk) * WPAD;
    for (int idx = threadIdx.x; idx < Dm*KDk; idx += 256) {
        int d = idx >> 4, k = idx & 15;
        dst[k*WPAD + d] = w[idx];
    }
}

// ==========================================================================
// Kernel 1: projections.  Block = (80-token chunk, head), 256 threads.
// thread (k = tid&15, tg = tid>>4): 5 tokens x 7 mats, fma2 inner loop.
// BOTH weight rows and q rows padded to 130 floats -> conflict-free LDS.64.
// ==========================================================================
#define PT_TOK 80
#define QPAD   130
#define K1_SMEM ((7*16*WPAD + PT_TOK*QPAD)*4)   // 99840 B

__global__ void __launch_bounds__(256) proj_kernel(const float* __restrict__ q)
{
    extern __shared__ float sm[];
    float* Wt = sm;                         // 112*130
    float* qs = sm + 7*KDk*WPAD;            // 80*130

    const int h    = blockIdx.y;
    const int base = blockIdx.x * PT_TOK;
    const int tid  = threadIdx.x;
    const int nTok = min(PT_TOK, NTOK - base);

    {   // stage padded weights (contiguous float2 copy, L2-hot)
        const float2* src = (const float2*)(g_Wt + (size_t)h*7*KDk*WPAD);
        float2*       dst = (float2*)Wt;
#pragma unroll
        for (int i = 0; i < 29; i++) {      // 29*256 = 7424 >= 7280
            int idx = tid + i*256;
            if (idx < 7*KDk*WPAD/2) dst[idx] = src[idx];
        }
    }
    {   // stage q rows with padding (float2 granularity)
        const float2* qg = (const float2*)(q + (size_t)base * Dm);
        const int n2 = nTok * (Dm/2);
        for (int idx = tid; idx < n2; idx += 256) {
            int t = idx >> 6, i = idx & 63;
            ((float2*)(qs + t*QPAD))[i] = qg[idx];
        }
    }
    __syncthreads();

    const int k  = tid & 15;
    const int tg = tid >> 4;                // 16 groups x 5 tokens
    const int t0 = tg * 5;

    u64 acc[5][7];
#pragma unroll
    for (int i = 0; i < 5; i++)
#pragma unroll
        for (int m = 0; m < 7; m++) acc[i][m] = 0ull;

    const u64* qr[5];
#pragma unroll
    for (int i = 0; i < 5; i++) qr[i] = (const u64*)(qs + (t0 + i)*QPAD);
    const u64* wr[7];
#pragma unroll
    for (int m = 0; m < 7; m++) wr[m] = (const u64*)(Wt + (m*16 + k)*WPAD);

#pragma unroll 2
    for (int d2 = 0; d2 < Dm/2; d2++) {
        u64 qv[5];
#pragma unroll
        for (int i = 0; i < 5; i++) qv[i] = qr[i][d2];
#pragma unroll
        for (int m = 0; m < 7; m++) {
            u64 w = wr[m][d2];
#pragma unroll
            for (int i = 0; i < 5; i++) acc[i][m] = fma2(qv[i], w, acc[i][m]);
        }
    }

#pragma unroll
    for (int i = 0; i < 5; i++) {
        if (t0 + i >= nTok) break;
        float s[7];
#pragma unroll
        for (int m = 0; m < 7; m++) { float x, y; upk(acc[i][m], x, y); s[m] = x + y; }
        const int token = base + t0 + i;
        const int b = token / Gg;
        const int g = token - b * Gg;
        const bool pick = (g >= 1 && g <= NPICK);
        const int idx = ((h*Bb + b)*Gg + g)*KDk + k;
        g_Qm[idx] = s[0] * SCL;
        g_K [idx] = s[1];
        g_V [idx] = s[2];
        g_QA[idx] = (pick ? s[3] : s[5]) * SCL;
        g_QB[idx] = (pick ? s[4] : s[6]) * SCL;
    }
}

// ==========================================================================
// Kernel 2: fused attention.  One block per (h,b), 512 threads, one q-row
// per thread.  Fixed-offset exp2 softmax, packed f32x2 dot + AV accumulate.
// Output written hv-major into g_heads2 (coalesced per-v columns).
// ==========================================================================
#define K2_SMEM (2*Gg*KDk*4)   // 64128 B

__global__ void __launch_bounds__(512) attn_kernel()
{
    extern __shared__ float sm[];

    const int b  = blockIdx.x;
    const int h  = blockIdx.y;
    const int tid = threadIdx.x;
    const int hb  = h*Bb + b;

    {   // stage K,V for this (h,b): 501 x 16 floats each
        const float4* Kg = (const float4*)(g_K + (size_t)hb * Gg * KDk);
        const float4* Vg = (const float4*)(g_V + (size_t)hb * Gg * KDk);
        float4* Ks4 = (float4*)sm;
        float4* Vs4 = (float4*)(sm + Gg*KDk);
        for (int i = tid; i < Gg*4; i += 512) { Ks4[i] = Kg[i]; Vs4[i] = Vg[i]; }
    }
    __syncthreads();

    const int qrow = tid;
    if (qrow >= Gg) return;

    const u64* Ks = (const u64*)sm;
    const u64* Vs = Ks + Gg*8;

    const int qidx = (hb*Gg + qrow)*KDk;
    u64 qm[8];
    {
        const u64* qp = (const u64*)(g_Qm + qidx);
#pragma unroll
        for (int j = 0; j < 8; j++) qm[j] = qp[j];
    }

    float l = 0.f;
    u64 o[8];
#pragma unroll
    for (int j = 0; j < 8; j++) o[j] = 0ull;

    // ---- main block: 501 keys, no mask ----
#pragma unroll 2
    for (int g = 0; g < Gg; g++) {
        const u64* kr = Ks + g*8;
        u64 a0 = mul2(qm[0], kr[0]);
        u64 a1 = mul2(qm[1], kr[1]);
        a0 = fma2(qm[2], kr[2], a0);
        a1 = fma2(qm[3], kr[3], a1);
        a0 = fma2(qm[4], kr[4], a0);
        a1 = fma2(qm[5], kr[5], a1);
        a0 = fma2(qm[6], kr[6], a0);
        a1 = fma2(qm[7], kr[7], a1);
        a0 = add2(a0, a1);
        float x, y; upk(a0, x, y);
        float s = x + y;
        float p = ex2f(s - M2OFF);
        l += p;
        u64 pp = dup2(p);
        const u64* vr = Vs + g*8;
#pragma unroll
        for (int j = 0; j < 8; j++) o[j] = fma2(pp, vr[j], o[j]);
    }

    // ---- extra blocks (rows 1..500 only), zmask: score==0 -> excluded ----
    if (qrow >= 1) {
        u64 qa[8], qb[8];
        {
            const u64* pa = (const u64*)(g_QA + qidx);
            const u64* pb = (const u64*)(g_QB + qidx);
#pragma unroll
            for (int j = 0; j < 8; j++) { qa[j] = pa[j]; qb[j] = pb[j]; }
        }
        const u64* Kp = Ks + 1*8;
        const u64* Vp = Vs + 1*8;
#pragma unroll 2
        for (int g = 0; g < NPICK; g++) {
            const u64* kr = Kp + g*8;
            u64 a0 = mul2(qa[0], kr[0]);
            u64 a1 = mul2(qa[1], kr[1]);
            a0 = fma2(qa[2], kr[2], a0);
            a1 = fma2(qa[3], kr[3], a1);
            a0 = fma2(qa[4], kr[4], a0);
            a1 = fma2(qa[5], kr[5], a1);
            a0 = fma2(qa[6], kr[6], a0);
            a1 = fma2(qa[7], kr[7], a1);
            a0 = add2(a0, a1);
            float x, y; upk(a0, x, y);
            float s = x + y;
            float p = ex2f(s - M2OFF);
            p = (s == 0.f) ? 0.f : p;
            l += p;
            u64 pp = dup2(p);
            const u64* vr = Vp + g*8;
#pragma unroll
            for (int j = 0; j < 8; j++) o[j] = fma2(pp, vr[j], o[j]);
        }
        const u64* Kd = Ks + (1+NPICK)*8;
        const u64* Vd = Vs + (1+NPICK)*8;
#pragma unroll 2
        for (int g = 0; g < NDEL; g++) {
            const u64* kr = Kd + g*8;
            u64 a0 = mul2(qb[0], kr[0]);
            u64 a1 = mul2(qb[1], kr[1]);
            a0 = fma2(qb[2], kr[2], a0);
            a1 = fma2(qb[3], kr[3], a1);
            a0 = fma2(qb[4], kr[4], a0);
            a1 = fma2(qb[5], kr[5], a1);
            a0 = fma2(qb[6], kr[6], a0);
            a1 = fma2(qb[7], kr[7], a1);
            a0 = add2(a0, a1);
            float x, y; upk(a0, x, y);
            float s = x + y;
            float p = ex2f(s - M2OFF);
            p = (s == 0.f) ? 0.f : p;
            l += p;
            u64 pp = dup2(p);
            const u64* vr = Vd + g*8;
#pragma unroll
            for (int j = 0; j < 8; j++) o[j] = fma2(pp, vr[j], o[j]);
        }
    }

    const float inv = 1.f / l;
    const u64 iv = dup2(inv);
    // hv-major write: g_heads2[b][h*16+v][qrow]
    float* hp = g_heads2 + ((size_t)b*128 + h*16)*GPAD + qrow;
#pragma unroll
    for (int j = 0; j < 8; j++) {
        float x, y; upk(mul2(o[j], iv), x, y);
        hp[(2*j  )*GPAD] = x;
        hp[(2*j+1)*GPAD] = y;
    }
}

// ==========================================================================
// Kernel 3: out[b,g,e] = sum_hv heads2[b][hv][g] * W_out[hv][e]
// Register-tiled GEMM.  Block = (32-token g-tile, b), 256 threads.
// Thread (elane, glane) computes 2g x 8e via 8 u64 fma2 accumulators.
// smem: W_out 128x130 (padded), A tile 128x34 (padded).  Conflict-free.
// ==========================================================================
#define OT_GT  32
#define A_PAD  34
#define W_PAD  130
#define K3_SMEM ((128*W_PAD + 128*A_PAD)*4)   // 83968 B

__global__ void __launch_bounds__(256) out_kernel(const float* __restrict__ Wo,
                                                  float* __restrict__ out)
{
    extern __shared__ float sm[];
    float* Bs = sm;                  // 128 x 130  (W_out)
    float* As = sm + 128*W_PAD;      // 128 x 34   (heads tile)

    const int b   = blockIdx.y;
    const int g0  = blockIdx.x * OT_GT;
    const int tid = threadIdx.x;

    {   // stage W_out: 128x128, rows padded to 130
        const float2* src = (const float2*)Wo;
        for (int i = tid; i < 128*64; i += 256) {
            int r = i >> 6, c = i & 63;
            *(float2*)(Bs + r*W_PAD + 2*c) = src[i];
        }
    }
    {   // stage A tile: heads2[b][hv][g0..g0+31], rows padded to 34
        // (cols >= Gg in g_heads2 are never written; zero-init -> safe)
        for (int i = tid; i < 128*16; i += 256) {
            int r = i >> 4, c = i & 15;
            *(float2*)(As + r*A_PAD + 2*c) =
                *(const float2*)(g_heads2 + ((size_t)b*128 + r)*GPAD + g0 + 2*c);
        }
    }
    __syncthreads();

    const int elane = tid & 15;      // 8 e-columns: e_j = 2*elane + 32*j (pairs)
    const int glane = tid >> 4;      // 2 g-rows: g0 + 2*glane, +1

    u64 acc[2][4];
#pragma unroll
    for (int gg = 0; gg < 2; gg++)
#pragma unroll
        for (int j = 0; j < 4; j++) acc[gg][j] = 0ull;

    const float* Ap = As + 2*glane;

#pragma unroll 4
    for (int hv = 0; hv < 128; hv++) {
        float a0 = Ap[hv*A_PAD];
        float a1 = Ap[hv*A_PAD + 1];
        u64 aa0 = dup2(a0);
        u64 aa1 = dup2(a1);
        const u64* br = (const u64*)(Bs + hv*W_PAD) + elane;
#pragma unroll
        for (int j = 0; j < 4; j++) {
            u64 bv = br[16*j];
            acc[0][j] = fma2(bv, aa0, acc[0][j]);
            acc[1][j] = fma2(bv, aa1, acc[1][j]);
        }
    }

#pragma unroll
    for (int gg = 0; gg < 2; gg++) {
        const int g = g0 + 2*glane + gg;
        if (g < Gg) {
            float* op = out + ((size_t)b*Gg + g)*Ee;
#pragma unroll
            for (int j = 0; j < 4; j++) {
                float x, y; upk(acc[gg][j], x, y);
                *(float2*)(op + 2*elane + 32*j) = make_float2(x, y);
            }
        }
    }
}

// ==========================================================================
extern "C" void kernel_launch(void* const* d_in, const int* in_sizes, int n_in,
                              void* d_out, int out_size)
{
    const float* q  = (const float*)d_in[0];
    const float* Wq = (const float*)d_in[1];
    const float* Wk = (const float*)d_in[2];
    const float* Wv = (const float*)d_in[3];
    const float* W1 = (const float*)d_in[4];
    const float* W2 = (const float*)d_in[5];
    const float* W3 = (const float*)d_in[6];
    const float* W4 = (const float*)d_in[7];
    const float* Wo = (const float*)d_in[8];
    float* out = (float*)d_out;

    cudaFuncSetAttribute(proj_kernel, cudaFuncAttributeMaxDynamicSharedMemorySize, K1_SMEM);
    cudaFuncSetAttribute(attn_kernel, cudaFuncAttributeMaxDynamicSharedMemorySize, K2_SMEM);
    cudaFuncSetAttribute(out_kernel,  cudaFuncAttributeMaxDynamicSharedMemorySize, K3_SMEM);

    dim3 g0(7, Hh);
    wprep_kernel<<<g0, 256>>>(Wq, Wk, Wv, W1, W2, W3, W4);

    dim3 g1((NTOK + PT_TOK - 1)/PT_TOK, Hh);        // (101, 8)
    proj_kernel<<<g1, 256, K1_SMEM>>>(q);

    dim3 g2(Bb, Hh);                                // (16, 8) x 512 threads
    attn_kernel<<<g2, 512, K2_SMEM>>>();

    dim3 g3((Gg + OT_GT - 1)/OT_GT, Bb);            // (16, 16)
    out_kernel<<<g3, 256, K3_SMEM>>>(Wo, out);
}